// round 1
// baseline (speedup 1.0000x reference)
#include <cuda_runtime.h>
#include <cstdint>

// Problem constants (DescrptSeA)
#define NF      2
#define NLOC    4096
#define NALL    4608
#define NNEI    138
#define SEC1    46      // type-0 neighbors: [0,46), type-1: [46,138)
#define MDIM    100
#define AXIS    16
#define NTHREADS 128

// ---------------------------------------------------------------------------
// dtype probe: reference declares int64 indices, but default JAX config emits
// int32. Detect from the data: if interpreted as int32 pairs, the odd words of
// an int64 buffer (values >= 0, < 2^31) are all zero. For nlist (values in
// [0,4608)) and atype (values in {0,1}) the false-positive probability of
// 512 consecutive zero odd-words under int32 is negligible.
// ---------------------------------------------------------------------------
__device__ int g_is64[2];

__global__ void probe_kernel(const unsigned* nlist_w, const unsigned* atype_w) {
    if (threadIdx.x == 0 && blockIdx.x == 0) {
        int nz = 0;
        for (int p = 0; p < 512; p++) nz += (nlist_w[2 * p + 1] != 0u);
        g_is64[0] = (nz == 0) ? 1 : 0;
        nz = 0;
        for (int p = 0; p < 512; p++) nz += (atype_w[2 * p + 1] != 0u);
        g_is64[1] = (nz == 0) ? 1 : 0;
    }
}

__device__ __forceinline__ float tanh_ap(float x) {
    float y;
    asm("tanh.approx.f32 %0, %1;" : "=f"(y) : "f"(x));
    return y;
}

__device__ __forceinline__ long long load_idx(const void* p, long long i, int is64) {
    if (is64) return ((const long long*)p)[i];
    return (long long)((const int*)p)[i];
}

struct SM {
    alignas(16) float env[NNEI][4];     // normalized env matrix rows
    alignas(16) float h0[NNEI][25];
    alignas(16) float h1[NNEI][52];     // padded to 52 for aligned float4 rows
    alignas(16) float w0[2][25];
    float b0[2][25];
    alignas(16) float w1[2][1250];      // [t][j*50+k]
    float b1[2][50];
    float b2[2][100];
    alignas(16) float xyz[4][MDIM];
};

__global__ __launch_bounds__(NTHREADS, 1)
void desc_kernel(const void* __restrict__ nlist_,
                 const float* __restrict__ coord,
                 const void* __restrict__ atype_,
                 const float* __restrict__ mean,
                 const float* __restrict__ stdv,
                 const float* __restrict__ w0,
                 const float* __restrict__ b0,
                 const float* __restrict__ w1,
                 const float* __restrict__ b1,
                 const float* __restrict__ w2,
                 const float* __restrict__ b2,
                 float* __restrict__ out)
{
    extern __shared__ unsigned char smem_raw[];
    SM& sm = *reinterpret_cast<SM*>(smem_raw);

    const int tid = threadIdx.x;
    const int row = blockIdx.x;            // 0 .. NF*NLOC-1
    const int f   = row >> 12;             // NLOC = 4096
    const int li  = row & (NLOC - 1);
    const int is64n = g_is64[0];
    const int is64a = g_is64[1];

    // ---- cooperative weight staging -------------------------------------
    for (int x = tid; x < 50; x += NTHREADS) {
        int t = x / 25, j = x % 25;
        sm.w0[t][j] = w0[x];
        sm.b0[t][j] = b0[x];
    }
    for (int x = tid; x < 2500; x += NTHREADS) sm.w1[x / 1250][x % 1250] = w1[x];
    for (int x = tid; x < 100;  x += NTHREADS) sm.b1[x / 50][x % 50]     = b1[x];
    for (int x = tid; x < 200;  x += NTHREADS) sm.b2[x / 100][x % 100]   = b2[x];

    // ---- stage 1: env matrix --------------------------------------------
    const long long ci = (long long)f * NALL + li;
    const float cx = coord[ci * 3 + 0];
    const float cy = coord[ci * 3 + 1];
    const float cz = coord[ci * 3 + 2];
    const int at = (int)load_idx(atype_, ci, is64a);

    for (int s0 = tid; s0 < NNEI; s0 += NTHREADS) {
        long long nb = load_idx(nlist_, (long long)row * NNEI + s0, is64n);
        bool valid = (nb >= 0);
        long long j = valid ? nb : 0;
        const float* cp = coord + ((long long)f * NALL + j) * 3;
        float dx = cp[0] - cx, dy = cp[1] - cy, dz = cp[2] - cz;
        float r = sqrtf(dx * dx + dy * dy + dz * dz);
        // switch function
        float uu = (r - 0.5f) * (1.0f / 5.5f);
        float vv = uu * uu * uu * (uu * (-6.0f * uu + 15.0f) - 10.0f) + 1.0f;
        float w = (r < 0.5f) ? 1.0f : ((r >= 6.0f) ? 0.0f : vv);
        if (!valid) w = 0.0f;
        float inv = 1.0f / (r + 0.01f);
        float a0 = inv * w;
        float aw = inv * inv * w;
        int base = (at * NNEI + s0) * 4;
        sm.env[s0][0] = (a0      - mean[base + 0]) / stdv[base + 0];
        sm.env[s0][1] = (dx * aw - mean[base + 1]) / stdv[base + 1];
        sm.env[s0][2] = (dy * aw - mean[base + 2]) / stdv[base + 2];
        sm.env[s0][3] = (dz * aw - mean[base + 3]) / stdv[base + 3];
    }
    __syncthreads();

    // ---- stage h0: 138 x 25 ---------------------------------------------
    for (int x = tid; x < NNEI * 25; x += NTHREADS) {
        int s0 = x / 25, j = x - s0 * 25;
        int t = (s0 >= SEC1);
        sm.h0[s0][j] = tanh_ap(sm.env[s0][0] * sm.w0[t][j] + sm.b0[t][j]);
    }
    __syncthreads();

    // ---- stage h1: 138 x 50 (25-FMA dot each) ---------------------------
    for (int x = tid; x < NNEI * 50; x += NTHREADS) {
        int s0 = x / 50, k = x - s0 * 50;
        int t = (s0 >= SEC1);
        float acc = sm.b1[t][k];
        const float* h0r = sm.h0[s0];
        const float* w1c = &sm.w1[t][k];  // stride 50 over j
        #pragma unroll
        for (int j = 0; j < 25; j++) acc += h0r[j] * w1c[j * 50];
        int km = (k < 25) ? k : (k - 25);
        sm.h1[s0][k] = tanh_ap(acc) + h0r[km];
    }
    __syncthreads();

    // ---- stage 2: gg = tanh(h1@w2 + b2) + [h1,h1]; xyz += env_s * gg ----
    float x0 = 0.f, x1 = 0.f, x2 = 0.f, x3 = 0.f;
    if (tid < MDIM) {
        const int m = tid;
        const int mm = (m < 50) ? m : (m - 50);
        #pragma unroll
        for (int t = 0; t < 2; t++) {
            float w2c[50];
            #pragma unroll
            for (int k = 0; k < 50; k++) w2c[k] = w2[t * 5000 + k * 100 + m];
            const float b2m = sm.b2[t][m];
            const int sbeg = t ? SEC1 : 0;
            const int send = t ? NNEI : SEC1;
            for (int s0 = sbeg; s0 < send; s0++) {
                const float* h1r = sm.h1[s0];
                float acc = b2m;
                #pragma unroll
                for (int k4 = 0; k4 < 48; k4 += 4) {
                    float4 h = *(const float4*)(h1r + k4);
                    acc += h.x * w2c[k4]     + h.y * w2c[k4 + 1]
                         + h.z * w2c[k4 + 2] + h.w * w2c[k4 + 3];
                }
                acc += h1r[48] * w2c[48] + h1r[49] * w2c[49];
                float g = tanh_ap(acc) + h1r[mm];
                float4 e = *(const float4*)(sm.env[s0]);
                x0 += e.x * g;
                x1 += e.y * g;
                x2 += e.z * g;
                x3 += e.w * g;
            }
        }
        const float sc = 1.0f / (float)NNEI;
        x0 *= sc; x1 *= sc; x2 *= sc; x3 *= sc;
        sm.xyz[0][m] = x0;
        sm.xyz[1][m] = x1;
        sm.xyz[2][m] = x2;
        sm.xyz[3][m] = x3;
    }
    __syncthreads();

    // ---- epilogue: res[m][a] = sum_d xyz[d][m]*xyz[d][a], a < 16 --------
    if (tid < MDIM) {
        const int m = tid;
        float* op = out + (long long)row * (MDIM * AXIS) + m * AXIS;
        #pragma unroll
        for (int a4 = 0; a4 < AXIS; a4 += 4) {
            float4 v;
            v.x = x0 * sm.xyz[0][a4 + 0] + x1 * sm.xyz[1][a4 + 0]
                + x2 * sm.xyz[2][a4 + 0] + x3 * sm.xyz[3][a4 + 0];
            v.y = x0 * sm.xyz[0][a4 + 1] + x1 * sm.xyz[1][a4 + 1]
                + x2 * sm.xyz[2][a4 + 1] + x3 * sm.xyz[3][a4 + 1];
            v.z = x0 * sm.xyz[0][a4 + 2] + x1 * sm.xyz[1][a4 + 2]
                + x2 * sm.xyz[2][a4 + 2] + x3 * sm.xyz[3][a4 + 2];
            v.w = x0 * sm.xyz[0][a4 + 3] + x1 * sm.xyz[1][a4 + 3]
                + x2 * sm.xyz[2][a4 + 3] + x3 * sm.xyz[3][a4 + 3];
            *(float4*)(op + a4) = v;
        }
    }
}

extern "C" void kernel_launch(void* const* d_in, const int* in_sizes, int n_in,
                              void* d_out, int out_size)
{
    const void*  nlist = d_in[0];
    const float* coord = (const float*)d_in[1];
    const void*  atype = d_in[2];
    const float* mean  = (const float*)d_in[3];
    const float* stdv  = (const float*)d_in[4];
    const float* w0    = (const float*)d_in[5];
    const float* b0    = (const float*)d_in[6];
    const float* w1    = (const float*)d_in[7];
    const float* b1    = (const float*)d_in[8];
    const float* w2    = (const float*)d_in[9];
    const float* b2    = (const float*)d_in[10];
    float* out = (float*)d_out;

    cudaFuncSetAttribute(desc_kernel,
                         cudaFuncAttributeMaxDynamicSharedMemorySize,
                         (int)sizeof(SM));

    probe_kernel<<<1, 32>>>((const unsigned*)nlist, (const unsigned*)atype);
    desc_kernel<<<NF * NLOC, NTHREADS, sizeof(SM)>>>(
        nlist, coord, atype, mean, stdv, w0, b0, w1, b1, w2, b2, out);
}

// round 2
// speedup vs baseline: 1.1463x; 1.1463x over previous
#include <cuda_runtime.h>
#include <cstdint>

// Problem constants (DescrptSeA)
#define NF      2
#define NLOC    4096
#define NALL    4608
#define NNEI    138
#define SEC1    46      // type-0 neighbors: [0,46), type-1: [46,138)
#define MDIM    100
#define AXIS    16
#define NTHREADS 256
#define SSPLIT  69      // stage-2 neighbor split point between thread groups

typedef unsigned long long ull;

// ---------------------------------------------------------------------------
// dtype probe: reference declares int64 indices, but JAX may emit int32.
// Detect from data: for an int64 buffer of small non-negative values the odd
// 32-bit words are all zero.
// ---------------------------------------------------------------------------
__device__ int g_is64[2];

__global__ void probe_kernel(const unsigned* nlist_w, const unsigned* atype_w) {
    if (threadIdx.x == 0 && blockIdx.x == 0) {
        int nz = 0;
        for (int p = 0; p < 512; p++) nz += (nlist_w[2 * p + 1] != 0u);
        g_is64[0] = (nz == 0) ? 1 : 0;
        nz = 0;
        for (int p = 0; p < 512; p++) nz += (atype_w[2 * p + 1] != 0u);
        g_is64[1] = (nz == 0) ? 1 : 0;
    }
}

__device__ __forceinline__ float tanh_ap(float x) {
    float y;
    asm("tanh.approx.f32 %0, %1;" : "=f"(y) : "f"(x));
    return y;
}

// ---- packed f32x2 helpers (Blackwell FFMA2 path) --------------------------
__device__ __forceinline__ ull pack2(float lo, float hi) {
    ull r;
    asm("mov.b64 %0, {%1, %2};" : "=l"(r) : "f"(lo), "f"(hi));
    return r;
}
__device__ __forceinline__ ull ffma2(ull a, ull b, ull c) {
    ull d;
    asm("fma.rn.f32x2 %0, %1, %2, %3;" : "=l"(d) : "l"(a), "l"(b), "l"(c));
    return d;
}
__device__ __forceinline__ ull fadd2(ull a, ull b) {
    ull d;
    asm("add.rn.f32x2 %0, %1, %2;" : "=l"(d) : "l"(a), "l"(b));
    return d;
}
__device__ __forceinline__ float hsum2(ull a) {
    float lo, hi;
    asm("mov.b64 {%0, %1}, %2;" : "=f"(lo), "=f"(hi) : "l"(a));
    return lo + hi;
}

__device__ __forceinline__ long long load_idx(const void* p, long long i, int is64) {
    if (is64) return ((const long long*)p)[i];
    return (long long)((const int*)p)[i];
}

struct SM {
    alignas(16) float env[NNEI][4];      // normalized env matrix rows
    alignas(16) float h1[NNEI][52];      // 50 + pad for aligned float4 rows
    alignas(8)  float h0[NNEI][26];      // 25 + zero pad (pair-aligned)
    alignas(8)  float w1T[2][50][26];    // transposed: [t][k][j], j pad->0
    alignas(16) float w0[2][25];
    float b0[2][25];
    float b1[2][50];
    float b2[2][100];
    alignas(16) float xyzp[2][4][MDIM];  // per-group partials
    alignas(16) float xyz[4][MDIM];
};

__global__ __launch_bounds__(NTHREADS, 2)
void desc_kernel(const void* __restrict__ nlist_,
                 const float* __restrict__ coord,
                 const void* __restrict__ atype_,
                 const float* __restrict__ mean,
                 const float* __restrict__ stdv,
                 const float* __restrict__ w0,
                 const float* __restrict__ b0,
                 const float* __restrict__ w1,
                 const float* __restrict__ b1,
                 const float* __restrict__ w2,
                 const float* __restrict__ b2,
                 float* __restrict__ out)
{
    extern __shared__ unsigned char smem_raw[];
    SM& sm = *reinterpret_cast<SM*>(smem_raw);

    const int tid = threadIdx.x;
    const int row = blockIdx.x;            // 0 .. NF*NLOC-1
    const int f   = row >> 12;             // NLOC = 4096
    const int li  = row & (NLOC - 1);
    const int is64n = g_is64[0];
    const int is64a = g_is64[1];

    // ---- cooperative weight staging -------------------------------------
    for (int x = tid; x < 50; x += NTHREADS) {
        int t = x / 25, j = x % 25;
        sm.w0[t][j] = w0[x];
        sm.b0[t][j] = b0[x];
    }
    // w1 transposed: w1T[t][k][j] = w1[t][j][k]; pad j=25 with zero
    for (int x = tid; x < 2 * 50 * 26; x += NTHREADS) {
        int t = x / (50 * 26);
        int r = x - t * 50 * 26;
        int k = r / 26, j = r - k * 26;
        sm.w1T[t][k][j] = (j < 25) ? w1[t * 1250 + j * 50 + k] : 0.0f;
    }
    for (int x = tid; x < 100;  x += NTHREADS) sm.b1[x / 50][x % 50]     = b1[x];
    for (int x = tid; x < 200;  x += NTHREADS) sm.b2[x / 100][x % 100]   = b2[x];

    // ---- stage 1: env matrix --------------------------------------------
    const long long ci = (long long)f * NALL + li;
    const float cx = coord[ci * 3 + 0];
    const float cy = coord[ci * 3 + 1];
    const float cz = coord[ci * 3 + 2];
    const int at = (int)load_idx(atype_, ci, is64a);

    if (tid < NNEI) {
        const int s0 = tid;
        long long nb = load_idx(nlist_, (long long)row * NNEI + s0, is64n);
        bool valid = (nb >= 0);
        long long j = valid ? nb : 0;
        const float* cp = coord + ((long long)f * NALL + j) * 3;
        float dx = cp[0] - cx, dy = cp[1] - cy, dz = cp[2] - cz;
        float r = sqrtf(dx * dx + dy * dy + dz * dz);
        float uu = (r - 0.5f) * (1.0f / 5.5f);
        float vv = uu * uu * uu * (uu * (-6.0f * uu + 15.0f) - 10.0f) + 1.0f;
        float w = (r < 0.5f) ? 1.0f : ((r >= 6.0f) ? 0.0f : vv);
        if (!valid) w = 0.0f;
        float inv = 1.0f / (r + 0.01f);
        float a0 = inv * w;
        float aw = inv * inv * w;
        int base = (at * NNEI + s0) * 4;
        sm.env[s0][0] = (a0      - mean[base + 0]) / stdv[base + 0];
        sm.env[s0][1] = (dx * aw - mean[base + 1]) / stdv[base + 1];
        sm.env[s0][2] = (dy * aw - mean[base + 2]) / stdv[base + 2];
        sm.env[s0][3] = (dz * aw - mean[base + 3]) / stdv[base + 3];
    }
    __syncthreads();

    // ---- stage h0: 138 x 25 (+ zero pad at j=25) -------------------------
    for (int x = tid; x < NNEI * 26; x += NTHREADS) {
        int s0 = x / 26, j = x - s0 * 26;
        int t = (s0 >= SEC1);
        sm.h0[s0][j] = (j < 25)
            ? tanh_ap(sm.env[s0][0] * sm.w0[t][j] + sm.b0[t][j])
            : 0.0f;
    }
    __syncthreads();

    // ---- stage h1: 138 x 50 via packed f32x2 (13 pairs over j) -----------
    for (int x = tid; x < NNEI * 50; x += NTHREADS) {
        int s0 = x / 50, k = x - s0 * 50;
        int t = (s0 >= SEC1);
        const ull* h0p = (const ull*)&sm.h0[s0][0];
        const ull* w1p = (const ull*)&sm.w1T[t][k][0];
        ull a0 = 0ull, a1 = 0ull, a2 = 0ull, a3 = 0ull;
        #pragma unroll
        for (int p = 0; p < 12; p += 4) {
            a0 = ffma2(h0p[p + 0], w1p[p + 0], a0);
            a1 = ffma2(h0p[p + 1], w1p[p + 1], a1);
            a2 = ffma2(h0p[p + 2], w1p[p + 2], a2);
            a3 = ffma2(h0p[p + 3], w1p[p + 3], a3);
        }
        a0 = ffma2(h0p[12], w1p[12], a0);   // pair 12 covers j=24 + zero pad
        a0 = fadd2(a0, a1);
        a2 = fadd2(a2, a3);
        float acc = hsum2(fadd2(a0, a2)) + sm.b1[t][k];
        int km = (k < 25) ? k : (k - 25);
        sm.h1[s0][k] = tanh_ap(acc) + sm.h0[s0][km];
    }
    __syncthreads();

    // ---- stage 2: gg = tanh(h1@w2 + b2) + [h1,h1]; xyz += env_s * gg -----
    // Two 128-thread groups split the neighbor range: [0,69) and [69,138).
    const int grp = tid >> 7;       // 0 or 1
    const int m   = tid & 127;
    float x0 = 0.f, x1 = 0.f, x2 = 0.f, x3 = 0.f;
    if (m < MDIM) {
        const int mm = (m < 50) ? m : (m - 50);
        auto run_seg = [&](int t, int sbeg, int send) {
            const float* w2g = w2 + t * 5000 + m;
            ull wp[25];
            #pragma unroll
            for (int p = 0; p < 25; p++)
                wp[p] = pack2(w2g[(2 * p) * 100], w2g[(2 * p + 1) * 100]);
            const float b2m = sm.b2[t][m];
            for (int s0 = sbeg; s0 < send; s0++) {
                const ull* hp = (const ull*)&sm.h1[s0][0];
                ull a0 = 0ull, a1 = 0ull, a2 = 0ull, a3 = 0ull;
                #pragma unroll
                for (int p = 0; p < 24; p += 4) {
                    a0 = ffma2(hp[p + 0], wp[p + 0], a0);
                    a1 = ffma2(hp[p + 1], wp[p + 1], a1);
                    a2 = ffma2(hp[p + 2], wp[p + 2], a2);
                    a3 = ffma2(hp[p + 3], wp[p + 3], a3);
                }
                a0 = ffma2(hp[24], wp[24], a0);
                a0 = fadd2(a0, a1);
                a2 = fadd2(a2, a3);
                float acc = hsum2(fadd2(a0, a2)) + b2m;
                float g = tanh_ap(acc) + sm.h1[s0][mm];
                float4 e = *(const float4*)(sm.env[s0]);
                x0 += e.x * g;
                x1 += e.y * g;
                x2 += e.z * g;
                x3 += e.w * g;
            }
        };
        if (grp == 0) {
            run_seg(0, 0, SEC1);          // type-0 neighbors
            run_seg(1, SEC1, SSPLIT);     // first chunk of type-1
        } else {
            run_seg(1, SSPLIT, NNEI);     // rest of type-1
        }
        sm.xyzp[grp][0][m] = x0;
        sm.xyzp[grp][1][m] = x1;
        sm.xyzp[grp][2][m] = x2;
        sm.xyzp[grp][3][m] = x3;
    }
    __syncthreads();

    // ---- combine partials + epilogue Gram product ------------------------
    if (tid < MDIM) {
        const int mI = tid;
        const float sc = 1.0f / (float)NNEI;
        x0 = (sm.xyzp[0][0][mI] + sm.xyzp[1][0][mI]) * sc;
        x1 = (sm.xyzp[0][1][mI] + sm.xyzp[1][1][mI]) * sc;
        x2 = (sm.xyzp[0][2][mI] + sm.xyzp[1][2][mI]) * sc;
        x3 = (sm.xyzp[0][3][mI] + sm.xyzp[1][3][mI]) * sc;
        sm.xyz[0][mI] = x0;
        sm.xyz[1][mI] = x1;
        sm.xyz[2][mI] = x2;
        sm.xyz[3][mI] = x3;
    }
    __syncthreads();

    if (tid < MDIM) {
        const int mI = tid;
        float* op = out + (long long)row * (MDIM * AXIS) + mI * AXIS;
        #pragma unroll
        for (int a4 = 0; a4 < AXIS; a4 += 4) {
            float4 v;
            v.x = x0 * sm.xyz[0][a4 + 0] + x1 * sm.xyz[1][a4 + 0]
                + x2 * sm.xyz[2][a4 + 0] + x3 * sm.xyz[3][a4 + 0];
            v.y = x0 * sm.xyz[0][a4 + 1] + x1 * sm.xyz[1][a4 + 1]
                + x2 * sm.xyz[2][a4 + 1] + x3 * sm.xyz[3][a4 + 1];
            v.z = x0 * sm.xyz[0][a4 + 2] + x1 * sm.xyz[1][a4 + 2]
                + x2 * sm.xyz[2][a4 + 2] + x3 * sm.xyz[3][a4 + 2];
            v.w = x0 * sm.xyz[0][a4 + 3] + x1 * sm.xyz[1][a4 + 3]
                + x2 * sm.xyz[2][a4 + 3] + x3 * sm.xyz[3][a4 + 3];
            *(float4*)(op + a4) = v;
        }
    }
}

extern "C" void kernel_launch(void* const* d_in, const int* in_sizes, int n_in,
                              void* d_out, int out_size)
{
    const void*  nlist = d_in[0];
    const float* coord = (const float*)d_in[1];
    const void*  atype = d_in[2];
    const float* mean  = (const float*)d_in[3];
    const float* stdv  = (const float*)d_in[4];
    const float* w0    = (const float*)d_in[5];
    const float* b0    = (const float*)d_in[6];
    const float* w1    = (const float*)d_in[7];
    const float* b1    = (const float*)d_in[8];
    const float* w2    = (const float*)d_in[9];
    const float* b2    = (const float*)d_in[10];
    float* out = (float*)d_out;

    cudaFuncSetAttribute(desc_kernel,
                         cudaFuncAttributeMaxDynamicSharedMemorySize,
                         (int)sizeof(SM));

    probe_kernel<<<1, 32>>>((const unsigned*)nlist, (const unsigned*)atype);
    desc_kernel<<<NF * NLOC, NTHREADS, sizeof(SM)>>>(
        nlist, coord, atype, mean, stdv, w0, b0, w1, b1, w2, b2, out);
}

// round 3
// speedup vs baseline: 1.4441x; 1.2598x over previous
#include <cuda_runtime.h>
#include <cstdint>

// Problem constants (DescrptSeA)
#define NF      2
#define NLOC    4096
#define NALL    4608
#define NROW    (NF * NLOC)
#define NNEI    138
#define SEC1    46      // type-0 neighbors: [0,46), type-1: [46,138)
#define MDIM    100
#define AXIS    16
#define NTHREADS 256
#define GRID    148

typedef unsigned long long ull;

// ---------------------------------------------------------------------------
// dtype probe: reference declares int64 indices, but JAX may emit int32.
// ---------------------------------------------------------------------------
__device__ int g_is64[2];

__global__ void probe_kernel(const unsigned* nlist_w, const unsigned* atype_w) {
    if (threadIdx.x == 0 && blockIdx.x == 0) {
        int nz = 0;
        for (int p = 0; p < 512; p++) nz += (nlist_w[2 * p + 1] != 0u);
        g_is64[0] = (nz == 0) ? 1 : 0;
        nz = 0;
        for (int p = 0; p < 512; p++) nz += (atype_w[2 * p + 1] != 0u);
        g_is64[1] = (nz == 0) ? 1 : 0;
    }
}

__device__ __forceinline__ float tanh_ap(float x) {
    float y;
    asm("tanh.approx.f32 %0, %1;" : "=f"(y) : "f"(x));
    return y;
}

// ---- packed f32x2 helpers --------------------------------------------------
__device__ __forceinline__ ull pack2(float lo, float hi) {
    ull r;
    asm("mov.b64 %0, {%1, %2};" : "=l"(r) : "f"(lo), "f"(hi));
    return r;
}
__device__ __forceinline__ ull ffma2(ull a, ull b, ull c) {
    ull d;
    asm("fma.rn.f32x2 %0, %1, %2, %3;" : "=l"(d) : "l"(a), "l"(b), "l"(c));
    return d;
}
__device__ __forceinline__ ull fadd2(ull a, ull b) {
    ull d;
    asm("add.rn.f32x2 %0, %1, %2;" : "=l"(d) : "l"(a), "l"(b));
    return d;
}
__device__ __forceinline__ float hsum2(ull a) {
    float lo, hi;
    asm("mov.b64 {%0, %1}, %2;" : "=f"(lo), "=f"(hi) : "l"(a));
    return lo + hi;
}

__device__ __forceinline__ long long load_idx(const void* p, long long i, int is64) {
    if (is64) return ((const long long*)p)[i];
    return (long long)((const int*)p)[i];
}

struct SM {
    alignas(16) float env[NNEI][4];      // normalized env rows
    alignas(16) float h1[NNEI][52];      // 50 + zero pad (16B rows)
    alignas(16) float h0[NNEI][28];      // 25 + zero pad (16B rows)
    alignas(16) float w1T[2][50][28];    // [t][k][j], j>=25 -> 0
    alignas(16) float w0s[2][25];
    float b0s[2][25];
    alignas(16) float xyzp[5][4][MDIM];  // stage-2 partials per chunk
    alignas(16) float xyz[4][MDIM];
};

__global__ __launch_bounds__(NTHREADS, 1)
void desc_kernel(const void* __restrict__ nlist_,
                 const float* __restrict__ coord,
                 const void* __restrict__ atype_,
                 const float* __restrict__ mean,
                 const float* __restrict__ stdv,
                 const float* __restrict__ w0,
                 const float* __restrict__ b0,
                 const float* __restrict__ w1,
                 const float* __restrict__ b1,
                 const float* __restrict__ w2,
                 const float* __restrict__ b2,
                 float* __restrict__ out)
{
    extern __shared__ unsigned char smem_raw[];
    SM& sm = *reinterpret_cast<SM*>(smem_raw);

    const int tid = threadIdx.x;
    const int is64n = g_is64[0];
    const int is64a = g_is64[1];

    // ---- one-time smem staging ------------------------------------------
    for (int x = tid; x < 50; x += NTHREADS) {
        int t = x / 25, j = x % 25;
        sm.w0s[t][j] = w0[x];
        sm.b0s[t][j] = b0[x];
    }
    // w1 transposed+padded: w1T[t][k][j] = w1[t][j][k], j>=25 -> 0
    for (int x = tid; x < 2 * 50 * 28; x += NTHREADS) {
        int t = x / (50 * 28);
        int r = x - t * 50 * 28;
        int k = r / 28, j = r - k * 28;
        sm.w1T[t][k][j] = (j < 25) ? w1[t * 1250 + j * 50 + k] : 0.0f;
    }
    // zero h1 pads once (never touched by compute afterwards)
    for (int x = tid; x < NNEI; x += NTHREADS) {
        sm.h1[x][50] = 0.0f;
        sm.h1[x][51] = 0.0f;
    }

    // ---- per-thread static roles ----------------------------------------
    // stage 2: 5 chunks x 50 col-pairs (cols p, p+50). Chunks type-aligned.
    const bool s2act = (tid < 250);
    const int p  = tid % 50;
    const int c  = tid / 50;
    int t2 = 0, sbeg2 = 0, send2 = 0;
    if (s2act) {
        if (c < 2) { t2 = 0; sbeg2 = c * 23;            send2 = sbeg2 + 23; }
        else       { t2 = 1; sbeg2 = 46 + (c - 2) * 31; send2 = sbeg2 + 31;
                     if (send2 > NNEI) send2 = NNEI; }
    }
    // pack w2 columns p and p+50 into registers (once per CTA)
    ull wpA[25], wpB[25];
    float b2A = 0.f, b2B = 0.f;
    if (s2act) {
        const float* wg = w2 + t2 * 5000;
        #pragma unroll
        for (int q = 0; q < 25; q++) {
            wpA[q] = pack2(wg[(2 * q) * 100 + p],      wg[(2 * q + 1) * 100 + p]);
            wpB[q] = pack2(wg[(2 * q) * 100 + p + 50], wg[(2 * q + 1) * 100 + p + 50]);
        }
        b2A = b2[t2 * 100 + p];
        b2B = b2[t2 * 100 + p + 50];
    }

    // stage h1: 9 segments x 25 k-pairs = 225 threads
    const bool h1act = (tid < 225);
    const int kp  = tid % 25;
    const int seg = tid / 25;
    int th1 = 0, hbeg = 0, hend = 0;
    if (h1act) {
        if (seg < 3) { th1 = 0; hbeg = (seg * 46) / 3;            hend = ((seg + 1) * 46) / 3; }
        else         { th1 = 1; hbeg = 46 + ((seg - 3) * 92) / 6; hend = 46 + ((seg - 2) * 92) / 6; }
    }
    const int k0 = 2 * kp, k1 = 2 * kp + 1;
    float b1k0 = 0.f, b1k1 = 0.f;
    if (h1act) {
        b1k0 = b1[th1 * 50 + k0];
        b1k1 = b1[th1 * 50 + k1];
    }
    const int km0 = (k0 < 25) ? k0 : k0 - 25;
    const int km1 = (k1 < 25) ? k1 : k1 - 25;

    __syncthreads();

    // =====================  persistent row loop  ==========================
    for (int row = blockIdx.x; row < NROW; row += GRID) {
        const int f  = row >> 12;
        const int li = row & (NLOC - 1);

        // ---- stage 1: env matrix ----------------------------------------
        const long long ci = (long long)f * NALL + li;
        if (tid < NNEI) {
            const int s0 = tid;
            const float cx = coord[ci * 3 + 0];
            const float cy = coord[ci * 3 + 1];
            const float cz = coord[ci * 3 + 2];
            const int at = (int)load_idx(atype_, ci, is64a);
            long long nb = load_idx(nlist_, (long long)row * NNEI + s0, is64n);
            bool valid = (nb >= 0);
            long long j = valid ? nb : 0;
            const float* cp = coord + ((long long)f * NALL + j) * 3;
            float dx = cp[0] - cx, dy = cp[1] - cy, dz = cp[2] - cz;
            float r = sqrtf(dx * dx + dy * dy + dz * dz);
            float uu = (r - 0.5f) * (1.0f / 5.5f);
            float vv = uu * uu * uu * (uu * (-6.0f * uu + 15.0f) - 10.0f) + 1.0f;
            float w = (r < 0.5f) ? 1.0f : ((r >= 6.0f) ? 0.0f : vv);
            if (!valid) w = 0.0f;
            float inv = 1.0f / (r + 0.01f);
            float a0 = inv * w;
            float aw = inv * inv * w;
            int base = (at * NNEI + s0) * 4;
            sm.env[s0][0] = (a0      - mean[base + 0]) / stdv[base + 0];
            sm.env[s0][1] = (dx * aw - mean[base + 1]) / stdv[base + 1];
            sm.env[s0][2] = (dy * aw - mean[base + 2]) / stdv[base + 2];
            sm.env[s0][3] = (dz * aw - mean[base + 3]) / stdv[base + 3];
        }
        __syncthreads();

        // ---- stage h0: 138 x 25 (+ zero pads to 28) ---------------------
        for (int x = tid; x < NNEI * 28; x += NTHREADS) {
            int s0 = x / 28, j = x - s0 * 28;
            int t = (s0 >= SEC1);
            sm.h0[s0][j] = (j < 25)
                ? tanh_ap(sm.env[s0][0] * sm.w0s[t][j] + sm.b0s[t][j])
                : 0.0f;
        }
        __syncthreads();

        // ---- stage h1: per-thread k-pair, weights in registers ----------
        if (h1act) {
            ulonglong2 wa[7], wb[7];
            const ulonglong2* w1a = (const ulonglong2*)&sm.w1T[th1][k0][0];
            const ulonglong2* w1b = (const ulonglong2*)&sm.w1T[th1][k1][0];
            #pragma unroll
            for (int v = 0; v < 7; v++) { wa[v] = w1a[v]; wb[v] = w1b[v]; }
            for (int s0 = hbeg; s0 < hend; s0++) {
                const ulonglong2* h0p = (const ulonglong2*)&sm.h0[s0][0];
                ull a0 = 0ull, a1 = 0ull, g0 = 0ull, g1 = 0ull;
                #pragma unroll
                for (int v = 0; v < 7; v++) {
                    ulonglong2 h = h0p[v];
                    a0 = ffma2(h.x, wa[v].x, a0);
                    a1 = ffma2(h.y, wa[v].y, a1);
                    g0 = ffma2(h.x, wb[v].x, g0);
                    g1 = ffma2(h.y, wb[v].y, g1);
                }
                float accA = hsum2(fadd2(a0, a1)) + b1k0;
                float accB = hsum2(fadd2(g0, g1)) + b1k1;
                float vA = tanh_ap(accA) + sm.h0[s0][km0];
                float vB = tanh_ap(accB) + sm.h0[s0][km1];
                *(ull*)&sm.h1[s0][k0] = pack2(vA, vB);
            }
        }
        __syncthreads();

        // ---- stage 2: gg = tanh(h1@w2+b2)+[h1,h1]; xyz += env^T g -------
        if (s2act) {
            float xA0 = 0.f, xA1 = 0.f, xA2 = 0.f, xA3 = 0.f;
            float xB0 = 0.f, xB1 = 0.f, xB2 = 0.f, xB3 = 0.f;
            for (int s0 = sbeg2; s0 < send2; s0++) {
                const ulonglong2* hp = (const ulonglong2*)&sm.h1[s0][0];
                ull last = *(const ull*)&sm.h1[s0][48];
                float resid = sm.h1[s0][p];
                float4 e = *(const float4*)sm.env[s0];
                ull aA0 = 0ull, aA1 = 0ull, aB0 = 0ull, aB1 = 0ull;
                #pragma unroll
                for (int v = 0; v < 12; v++) {
                    ulonglong2 h = hp[v];
                    aA0 = ffma2(h.x, wpA[2 * v],     aA0);
                    aA1 = ffma2(h.y, wpA[2 * v + 1], aA1);
                    aB0 = ffma2(h.x, wpB[2 * v],     aB0);
                    aB1 = ffma2(h.y, wpB[2 * v + 1], aB1);
                }
                aA0 = ffma2(last, wpA[24], aA0);
                aB0 = ffma2(last, wpB[24], aB0);
                float accA = hsum2(fadd2(aA0, aA1)) + b2A;
                float accB = hsum2(fadd2(aB0, aB1)) + b2B;
                float gA = tanh_ap(accA) + resid;
                float gB = tanh_ap(accB) + resid;
                xA0 += e.x * gA; xA1 += e.y * gA; xA2 += e.z * gA; xA3 += e.w * gA;
                xB0 += e.x * gB; xB1 += e.y * gB; xB2 += e.z * gB; xB3 += e.w * gB;
            }
            sm.xyzp[c][0][p] = xA0;  sm.xyzp[c][0][p + 50] = xB0;
            sm.xyzp[c][1][p] = xA1;  sm.xyzp[c][1][p + 50] = xB1;
            sm.xyzp[c][2][p] = xA2;  sm.xyzp[c][2][p + 50] = xB2;
            sm.xyzp[c][3][p] = xA3;  sm.xyzp[c][3][p + 50] = xB3;
        }
        __syncthreads();

        // ---- combine partials -------------------------------------------
        float x0, x1, x2, x3;
        if (tid < MDIM) {
            const float sc = 1.0f / (float)NNEI;
            x0 = x1 = x2 = x3 = 0.f;
            #pragma unroll
            for (int cc = 0; cc < 5; cc++) {
                x0 += sm.xyzp[cc][0][tid];
                x1 += sm.xyzp[cc][1][tid];
                x2 += sm.xyzp[cc][2][tid];
                x3 += sm.xyzp[cc][3][tid];
            }
            x0 *= sc; x1 *= sc; x2 *= sc; x3 *= sc;
            sm.xyz[0][tid] = x0;
            sm.xyz[1][tid] = x1;
            sm.xyz[2][tid] = x2;
            sm.xyz[3][tid] = x3;
        }
        __syncthreads();

        // ---- epilogue Gram product --------------------------------------
        if (tid < MDIM) {
            float* op = out + (long long)row * (MDIM * AXIS) + tid * AXIS;
            #pragma unroll
            for (int a4 = 0; a4 < AXIS; a4 += 4) {
                float4 v;
                v.x = x0 * sm.xyz[0][a4 + 0] + x1 * sm.xyz[1][a4 + 0]
                    + x2 * sm.xyz[2][a4 + 0] + x3 * sm.xyz[3][a4 + 0];
                v.y = x0 * sm.xyz[0][a4 + 1] + x1 * sm.xyz[1][a4 + 1]
                    + x2 * sm.xyz[2][a4 + 1] + x3 * sm.xyz[3][a4 + 1];
                v.z = x0 * sm.xyz[0][a4 + 2] + x1 * sm.xyz[1][a4 + 2]
                    + x2 * sm.xyz[2][a4 + 2] + x3 * sm.xyz[3][a4 + 2];
                v.w = x0 * sm.xyz[0][a4 + 3] + x1 * sm.xyz[1][a4 + 3]
                    + x2 * sm.xyz[2][a4 + 3] + x3 * sm.xyz[3][a4 + 3];
                *(float4*)(op + a4) = v;
            }
        }
        __syncthreads();
    }
}

extern "C" void kernel_launch(void* const* d_in, const int* in_sizes, int n_in,
                              void* d_out, int out_size)
{
    const void*  nlist = d_in[0];
    const float* coord = (const float*)d_in[1];
    const void*  atype = d_in[2];
    const float* mean  = (const float*)d_in[3];
    const float* stdv  = (const float*)d_in[4];
    const float* w0    = (const float*)d_in[5];
    const float* b0    = (const float*)d_in[6];
    const float* w1    = (const float*)d_in[7];
    const float* b1    = (const float*)d_in[8];
    const float* w2    = (const float*)d_in[9];
    const float* b2    = (const float*)d_in[10];
    float* out = (float*)d_out;

    cudaFuncSetAttribute(desc_kernel,
                         cudaFuncAttributeMaxDynamicSharedMemorySize,
                         (int)sizeof(SM));

    probe_kernel<<<1, 32>>>((const unsigned*)nlist, (const unsigned*)atype);
    desc_kernel<<<GRID, NTHREADS, sizeof(SM)>>>(
        nlist, coord, atype, mean, stdv, w0, b0, w1, b1, w2, b2, out);
}